// round 8
// baseline (speedup 1.0000x reference)
#include <cuda_runtime.h>
#include <cuda_bf16.h>
#include <cuda_fp8.h>
#include <cstdint>

#define BB 64
#define CC 384
#define C2 192
#define HW 1024
#define CR 24
#define P24K 24576
#define NTOK 65536
#define HID 1536
#define KP 80   // padded smem row bytes for BK=64 fp8

__device__ float   g_p[BB*CC];
__device__ float   g_params[BB*P24K];
__device__ float   g_y[(size_t)BB*CC*HW];
__device__ uint8_t g_alnq[(size_t)NTOK*CC];      // e4m3 LN'd activations (token-major)
__device__ uint8_t g_hidq[(size_t)NTOK*HID];     // e4m3 8*gelu(hidden)
__device__ uint8_t g_w1q[HID*CC];                // e4m3 16*w1
__device__ uint8_t g_w2q[CC*HID];                // e4m3 16*w2

__device__ __forceinline__ unsigned smem_u32(const void* p){return (unsigned)__cvta_generic_to_shared(p);}
__device__ __forceinline__ void cp16(void* s,const void* g){
    asm volatile("cp.async.cg.shared.global [%0], [%1], 16;\n"::"r"(smem_u32(s)),"l"(g));}
__device__ __forceinline__ void cp_commit(){asm volatile("cp.async.commit_group;\n");}
__device__ __forceinline__ void cp_wait1(){asm volatile("cp.async.wait_group 1;\n");}
__device__ __forceinline__ void cp_wait0(){asm volatile("cp.async.wait_group 0;\n");}
__device__ __forceinline__ void ldm_x4(unsigned addr,unsigned&r0,unsigned&r1,unsigned&r2,unsigned&r3){
    asm volatile("ldmatrix.sync.aligned.m8n8.x4.shared.b16 {%0,%1,%2,%3}, [%4];\n"
                 :"=r"(r0),"=r"(r1),"=r"(r2),"=r"(r3):"r"(addr));}
__device__ __forceinline__ void mma_fp8(float* c,unsigned a0,unsigned a1,unsigned a2,unsigned a3,
                                        unsigned b0,unsigned b1){
    asm volatile(
        "mma.sync.aligned.m16n8k32.row.col.f32.e4m3.e4m3.f32 "
        "{%0,%1,%2,%3},{%4,%5,%6,%7},{%8,%9},{%0,%1,%2,%3};\n"
        :"+f"(c[0]),"+f"(c[1]),"+f"(c[2]),"+f"(c[3])
        :"r"(a0),"r"(a1),"r"(a2),"r"(a3),"r"(b0),"r"(b1));}
__device__ __forceinline__ uint8_t f2e4(float v){
    return (uint8_t)__nv_cvt_float_to_fp8(v,__NV_SATFINITE,__NV_E4M3);}

// ---------------- k0: weights -> fp8 (x16) ----------------
__global__ void __launch_bounds__(256) cvt_w_kernel(const float* __restrict__ w1,
                                                    const float* __restrict__ w2){
    int i=blockIdx.x*256+threadIdx.x;
    if(i<HID*CC){
        g_w1q[i]=f2e4(w1[i]*16.0f);
        g_w2q[i]=f2e4(w2[i]*16.0f);
    }
}

// ---------------- k1: spatial mean pool ----------------
__global__ void __launch_bounds__(256) pool_kernel(const float* __restrict__ x){
    const float4* xr=reinterpret_cast<const float4*>(x+(size_t)blockIdx.x*HW);
    float4 v=xr[threadIdx.x];
    float s=v.x+v.y+v.z+v.w;
    #pragma unroll
    for(int o=16;o>0;o>>=1) s+=__shfl_down_sync(0xffffffffu,s,o);
    __shared__ float ws[8];
    if((threadIdx.x&31)==0) ws[threadIdx.x>>5]=s;
    __syncthreads();
    if(threadIdx.x<8){
        float t=ws[threadIdx.x];
        #pragma unroll
        for(int o=4;o>0;o>>=1) t+=__shfl_down_sync(0xffu,t,o);
        if(threadIdx.x==0) g_p[blockIdx.x]=t*(1.0f/1024.0f);
    }
}

// ---------------- k2: per-batch dynamic params ----------------
__global__ void __launch_bounds__(256) params_kernel(
    const float* __restrict__ kp_w1,const float* __restrict__ bng,const float* __restrict__ bnb,
    const float* __restrict__ bnm,const float* __restrict__ bnv,const float* __restrict__ kp_w2,
    const float* __restrict__ kp_b2,const float* __restrict__ fn_std,const float* __restrict__ fn_mean){
    int tid=threadIdx.x,b=blockIdx.x;
    __shared__ float ps[CC]; __shared__ float hs[CR];
    __shared__ float r1[256],r2[256]; __shared__ float uS,invS;
    for(int i=tid;i<CC;i+=256) ps[i]=g_p[b*CC+i];
    __syncthreads();
    if(tid<CR){
        float s=0.f; const float* wr=kp_w1+tid*CC;
        #pragma unroll 8
        for(int c=0;c<CC;++c) s+=ps[c]*wr[c];
        s=(s-bnm[tid])*rsqrtf(bnv[tid]+1e-5f)*bng[tid]+bnb[tid];
        hs[tid]=fmaxf(s,0.0f);
    }
    __syncthreads();
    float* gp=g_params+(size_t)b*P24K;
    float s1=0.f,s2=0.f;
    for(int i=tid;i<P24K;i+=256){
        const float* wr=kp_w2+(size_t)i*CR;
        float v=kp_b2[i];
        #pragma unroll
        for(int j=0;j<CR;++j) v+=hs[j]*wr[j];
        gp[i]=v; s1+=v; s2+=v*v;
    }
    r1[tid]=s1; r2[tid]=s2; __syncthreads();
    for(int o=128;o>0;o>>=1){ if(tid<o){r1[tid]+=r1[tid+o]; r2[tid]+=r2[tid+o];} __syncthreads(); }
    if(tid==0){
        float u=r1[0]*(1.0f/P24K);
        float var=r2[0]*(1.0f/P24K)-u*u;
        uS=u; invS=rsqrtf(var+1e-12f);
    }
    __syncthreads();
    float u=uS,inv=invS;
    for(int i=tid;i<P24K;i+=256){ float v=gp[i]; gp[i]=(v-u)*inv*fn_std[i]+fn_mean[i]; }
}

// ---------------- k3: circular conv + PE + bias (shfl-rotated taps) ----------------
__global__ void __launch_bounds__(256) conv_kernel(const float* __restrict__ x,
                                                   const float* __restrict__ bias){
    __shared__ float tile[32*33];
    __shared__ float pe_s[32];
    int tid=threadIdx.x,bc=blockIdx.x;
    int b=bc/CC,ch=bc%CC;
    const float* pb=g_params+(size_t)b*P24K;
    bool modeH=(ch<C2);
    const float* kb=modeH?(pb+(2*C2+ch)*32):(pb+(3*C2+(ch-C2))*32);
    const float* pe=modeH?(pb+ch*32):(pb+(C2+(ch-C2))*32);
    if(tid<32) pe_s[tid]=pe[tid];
    int lane=tid&31,h0=tid>>5;
    float kv=__ldg(&kb[lane]);
    __syncthreads();
    const float* xb=x+(size_t)bc*HW;
    #pragma unroll
    for(int r=0;r<4;++r){
        int idx=tid+r*256,g=idx>>5,w=idx&31;
        tile[g*33+w]=xb[idx]+(modeH?pe_s[g]:pe_s[w]);
    }
    __syncthreads();
    float bi=__ldg(&bias[ch]);
    float a0=0.f,a1=0.f,a2=0.f,a3=0.f,krot[32];
    if(modeH){
        #pragma unroll
        for(int g=0;g<32;++g) krot[g]=__shfl_sync(0xffffffffu,kv,(g-h0)&31);
        #pragma unroll
        for(int g=0;g<32;++g){
            float tv=tile[g*33+lane];
            a0+=krot[g]*tv;           a1+=krot[(g-8)&31]*tv;
            a2+=krot[(g-16)&31]*tv;   a3+=krot[(g-24)&31]*tv;
        }
    }else{
        #pragma unroll
        for(int v=0;v<32;++v) krot[v]=__shfl_sync(0xffffffffu,kv,(v-lane)&31);
        #pragma unroll
        for(int v=0;v<32;++v){
            float kvv=krot[v];
            a0+=kvv*tile[h0*33+v];        a1+=kvv*tile[(h0+8)*33+v];
            a2+=kvv*tile[(h0+16)*33+v];   a3+=kvv*tile[(h0+24)*33+v];
        }
    }
    float* yo=g_y+(size_t)bc*HW;
    yo[h0*32+lane]=a0+bi;        yo[(h0+8)*32+lane]=a1+bi;
    yo[(h0+16)*32+lane]=a2+bi;   yo[(h0+24)*32+lane]=a3+bi;
}

// ---------------- k4: channel LN -> token-major fp8 ----------------
__global__ void __launch_bounds__(256) ln_kernel(const float* __restrict__ ln_w,
                                                 const float* __restrict__ ln_b){
    int tid=threadIdx.x;
    int tok0=blockIdx.x*32;
    int b=tok0>>10,hw0=tok0&1023;
    int j=tid&31,cg=tid>>5;
    const float* yb=g_y+(size_t)b*CC*HW+hw0+j;
    float vals[48],s1=0.f,s2=0.f;
    #pragma unroll
    for(int i=0;i<48;++i){
        int c=cg+i*8;
        float v=yb[(size_t)c*HW];
        vals[i]=v; s1+=v; s2+=v*v;
    }
    __shared__ float rs1[8][32],rs2[8][32],muS[32],rstdS[32];
    rs1[cg][j]=s1; rs2[cg][j]=s2;
    __syncthreads();
    if(tid<32){
        float a=0.f,q=0.f;
        #pragma unroll
        for(int g=0;g<8;++g){a+=rs1[g][tid]; q+=rs2[g][tid];}
        float mu=a*(1.0f/CC);
        float var=q*(1.0f/CC)-mu*mu;
        muS[tid]=mu; rstdS[tid]=rsqrtf(var+1e-6f);
    }
    __syncthreads();
    __shared__ uint8_t smo[32*400];
    float mu=muS[j],rsd=rstdS[j];
    #pragma unroll
    for(int i=0;i<48;++i){
        int c=cg+i*8;
        float t=(vals[i]-mu)*rsd*ln_w[c]+ln_b[c];
        smo[j*400+c]=f2e4(t);
    }
    __syncthreads();
    uint32_t* ao=reinterpret_cast<uint32_t*>(g_alnq+(size_t)tok0*CC);
    for(int idx=tid;idx<32*96;idx+=256){
        int jj=idx/96,c4=(idx-jj*96)*4;
        const uint8_t* sr=smo+jj*400+c4;
        ao[idx]=(uint32_t)sr[0]|((uint32_t)sr[1]<<8)|((uint32_t)sr[2]<<16)|((uint32_t)sr[3]<<24);
    }
}

// ---------------- fp8 GEMM mainloop: 128x128xK, BK=64 fp8, 8 warps 4x2 ----------------
template<int KDIM>
__device__ __forceinline__ void gemm_tile(const uint8_t* __restrict__ A,
                                          const uint8_t* __restrict__ W,
                                          int mBase,int nBase,float acc[2][8][4]){
    __shared__ uint8_t As[2][128][KP];
    __shared__ uint8_t Ws[2][128][KP];
    const int tid=threadIdx.x;
    const int lane=tid&31,warp=tid>>5;
    const int wm=(warp&3)*32,wn=(warp>>2)*64;
    constexpr int KT=KDIM/64;

    // 128 rows x 64 bytes per tile: 512 (row,seg16) items, two tiles per item.
    auto load_stage=[&](int s,int kt){
        int k0=kt*64;
        #pragma unroll
        for(int i=tid;i<512;i+=256){
            int row=i>>2,seg=(i&3)*16;
            cp16(&As[s][row][seg],A+(size_t)(mBase+row)*KDIM+k0+seg);
            cp16(&Ws[s][row][seg],W+(size_t)(nBase+row)*KDIM+k0+seg);
        }
        cp_commit();
    };

    load_stage(0,0);
    for(int kt=0;kt<KT;++kt){
        int s=kt&1;
        if(kt+1<KT){ load_stage(s^1,kt+1); cp_wait1(); }
        else       { cp_wait0(); }
        __syncthreads();
        #pragma unroll
        for(int kk=0;kk<2;++kk){
            unsigned a[2][4],bq[4][4];
            #pragma unroll
            for(int mi=0;mi<2;++mi)
                ldm_x4(smem_u32(&As[s][wm+mi*16+(lane&15)][kk*32+(lane>>4)*16]),
                       a[mi][0],a[mi][1],a[mi][2],a[mi][3]);
            #pragma unroll
            for(int nq=0;nq<4;++nq)
                ldm_x4(smem_u32(&Ws[s][wn+nq*16+(lane&15)][kk*32+(lane>>4)*16]),
                       bq[nq][0],bq[nq][1],bq[nq][2],bq[nq][3]);
            #pragma unroll
            for(int mi=0;mi<2;++mi)
                #pragma unroll
                for(int ni=0;ni<8;++ni){
                    int nq=ni>>1,hp=ni&1;
                    mma_fp8(acc[mi][ni],a[mi][0],a[mi][1],a[mi][2],a[mi][3],
                            bq[nq][hp],bq[nq][2+hp]);
                }
        }
        __syncthreads();
    }
}

// ---------------- k5: GEMM1 (aln @ 16w1^T)/16 + b1 + GELU -> 8*fp8 ----------------
__global__ void __launch_bounds__(256) gemm1_kernel(const float* __restrict__ b1){
    float acc[2][8][4];
    #pragma unroll
    for(int i=0;i<2;++i)
        #pragma unroll
        for(int j=0;j<8;++j)
            #pragma unroll
            for(int k=0;k<4;++k) acc[i][j][k]=0.f;

    int mBase=blockIdx.y*128,nBase=blockIdx.x*128;
    gemm_tile<CC>(g_alnq,g_w1q,mBase,nBase,acc);

    int lane=threadIdx.x&31,warp=threadIdx.x>>5;
    int wm=mBase+(warp&3)*32,wn=nBase+(warp>>2)*64;
    const float ds=1.0f/16.0f;
    #pragma unroll
    for(int mi=0;mi<2;++mi)
        #pragma unroll
        for(int ni=0;ni<8;++ni){
            int n=wn+ni*8+(lane&3)*2;
            float bn0=__ldg(&b1[n]),bn1=__ldg(&b1[n+1]);
            int m=wm+mi*16+(lane>>2);
            float c0=acc[mi][ni][0]*ds+bn0;
            float c1=acc[mi][ni][1]*ds+bn1;
            float c2=acc[mi][ni][2]*ds+bn0;
            float c3=acc[mi][ni][3]*ds+bn1;
            c0=0.5f*c0*(1.0f+erff(c0*0.70710678f));
            c1=0.5f*c1*(1.0f+erff(c1*0.70710678f));
            c2=0.5f*c2*(1.0f+erff(c2*0.70710678f));
            c3=0.5f*c3*(1.0f+erff(c3*0.70710678f));
            uint16_t p0=(uint16_t)f2e4(c0*8.0f)|((uint16_t)f2e4(c1*8.0f)<<8);
            uint16_t p1=(uint16_t)f2e4(c2*8.0f)|((uint16_t)f2e4(c3*8.0f)<<8);
            *reinterpret_cast<uint16_t*>(&g_hidq[(size_t)m*HID+n])=p0;
            *reinterpret_cast<uint16_t*>(&g_hidq[(size_t)(m+8)*HID+n])=p1;
        }
}

// ---------------- k6: GEMM2 (8hid @ 16w2^T)/128 + b2, out = x + gamma*t ----------------
__global__ void __launch_bounds__(256) gemm2_kernel(const float* __restrict__ x,
                                                    const float* __restrict__ b2,
                                                    const float* __restrict__ gamma,
                                                    float* __restrict__ out){
    float acc[2][8][4];
    #pragma unroll
    for(int i=0;i<2;++i)
        #pragma unroll
        for(int j=0;j<8;++j)
            #pragma unroll
            for(int k=0;k<4;++k) acc[i][j][k]=0.f;

    int mBase=blockIdx.y*128,nBase=blockIdx.x*128;
    gemm_tile<HID>(g_hidq,g_w2q,mBase,nBase,acc);

    int lane=threadIdx.x&31,warp=threadIdx.x>>5;
    int wm=mBase+(warp&3)*32,wn=nBase+(warp>>2)*64;
    const float ds=1.0f/128.0f;
    #pragma unroll
    for(int mi=0;mi<2;++mi)
        #pragma unroll
        for(int ni=0;ni<8;++ni){
            int n=wn+ni*8+(lane&3)*2;
            float bb0=__ldg(&b2[n]),bb1=__ldg(&b2[n+1]);
            float gm0=__ldg(&gamma[n]),gm1=__ldg(&gamma[n+1]);
            int m0=wm+mi*16+(lane>>2);
            #pragma unroll
            for(int half=0;half<2;++half){
                int m=m0+half*8;
                float v0=acc[mi][ni][half*2+0]*ds+bb0;
                float v1=acc[mi][ni][half*2+1]*ds+bb1;
                int b=m>>10,hw=m&1023;
                size_t i0=((size_t)(b*CC+n)<<10)+hw;
                out[i0]     =x[i0]     +gm0*v0;
                out[i0+1024]=x[i0+1024]+gm1*v1;
            }
        }
}

// ---------------- launch ----------------
extern "C" void kernel_launch(void* const* d_in, const int* in_sizes, int n_in,
                              void* d_out, int out_size) {
    const float* x       = (const float*)d_in[0];
    const float* kp_w1   = (const float*)d_in[1];
    const float* bng     = (const float*)d_in[2];
    const float* bnb     = (const float*)d_in[3];
    const float* bnm     = (const float*)d_in[4];
    const float* bnv     = (const float*)d_in[5];
    const float* kp_w2   = (const float*)d_in[6];
    const float* kp_b2   = (const float*)d_in[7];
    const float* fn_std  = (const float*)d_in[8];
    const float* fn_mean = (const float*)d_in[9];
    const float* bias    = (const float*)d_in[10];
    const float* ln_w    = (const float*)d_in[11];
    const float* ln_b    = (const float*)d_in[12];
    const float* w1      = (const float*)d_in[13];
    const float* b1      = (const float*)d_in[14];
    const float* w2      = (const float*)d_in[15];
    const float* b2      = (const float*)d_in[16];
    const float* gamma   = (const float*)d_in[17];
    float* out = (float*)d_out;

    cvt_w_kernel<<<(HID*CC+255)/256,256>>>(w1,w2);
    pool_kernel<<<BB*CC,256>>>(x);
    params_kernel<<<BB,256>>>(kp_w1,bng,bnb,bnm,bnv,kp_w2,kp_b2,fn_std,fn_mean);
    conv_kernel<<<BB*CC,256>>>(x,bias);
    ln_kernel<<<NTOK/32,256>>>(ln_w,ln_b);
    gemm1_kernel<<<dim3(HID/128,NTOK/128),256>>>(b1);
    gemm2_kernel<<<dim3(CC/128,NTOK/128),256>>>(x,b2,gamma,out);
}

// round 9
// speedup vs baseline: 1.1171x; 1.1171x over previous
#include <cuda_runtime.h>
#include <cuda_bf16.h>
#include <cstdint>

#define BB 64
#define CC 384
#define C2 192
#define HW 1024
#define CR 24
#define P24K 24576
#define NTOK 65536
#define HID 1536
#define KPAD 40        // bf16 elems per padded smem row (BK=32 + 8 pad)
#define NS 4           // pipeline stages
#define GEMM_SMEM (NS*128*KPAD*2*2)   // 81920 B

__device__ float          g_p[BB*CC];
__device__ float          g_params[BB*P24K];
__device__ float          g_y[(size_t)BB*CC*HW];
__device__ __nv_bfloat16  g_aln[(size_t)NTOK*CC];
__device__ __nv_bfloat16  g_hid[(size_t)NTOK*HID];
__device__ __nv_bfloat16  g_w1b[HID*CC];
__device__ __nv_bfloat16  g_w2b[CC*HID];

__device__ __forceinline__ unsigned smem_u32(const void* p){return (unsigned)__cvta_generic_to_shared(p);}
__device__ __forceinline__ void cp16(void* s,const void* g){
    asm volatile("cp.async.cg.shared.global [%0], [%1], 16;\n"::"r"(smem_u32(s)),"l"(g));}
__device__ __forceinline__ void cp_commit(){asm volatile("cp.async.commit_group;\n");}
template<int N> __device__ __forceinline__ void cp_wait(){asm volatile("cp.async.wait_group %0;\n"::"n"(N));}
__device__ __forceinline__ void ldm_x4(unsigned addr,unsigned&r0,unsigned&r1,unsigned&r2,unsigned&r3){
    asm volatile("ldmatrix.sync.aligned.m8n8.x4.shared.b16 {%0,%1,%2,%3}, [%4];\n"
                 :"=r"(r0),"=r"(r1),"=r"(r2),"=r"(r3):"r"(addr));}
__device__ __forceinline__ void mma16816(float* c,unsigned a0,unsigned a1,unsigned a2,unsigned a3,
                                         unsigned b0,unsigned b1){
    asm volatile(
        "mma.sync.aligned.m16n8k16.row.col.f32.bf16.bf16.f32 "
        "{%0,%1,%2,%3},{%4,%5,%6,%7},{%8,%9},{%0,%1,%2,%3};\n"
        :"+f"(c[0]),"+f"(c[1]),"+f"(c[2]),"+f"(c[3])
        :"r"(a0),"r"(a1),"r"(a2),"r"(a3),"r"(b0),"r"(b1));}

// ---------------- k0: weights -> bf16 ----------------
__global__ void __launch_bounds__(256) cvt_w_kernel(const float* __restrict__ w1,
                                                    const float* __restrict__ w2){
    int i=blockIdx.x*256+threadIdx.x;
    if(i<HID*CC){
        g_w1b[i]=__float2bfloat16(w1[i]);
        g_w2b[i]=__float2bfloat16(w2[i]);
    }
}

// ---------------- k1: spatial mean pool ----------------
__global__ void __launch_bounds__(256) pool_kernel(const float* __restrict__ x){
    const float4* xr=reinterpret_cast<const float4*>(x+(size_t)blockIdx.x*HW);
    float4 v=xr[threadIdx.x];
    float s=v.x+v.y+v.z+v.w;
    #pragma unroll
    for(int o=16;o>0;o>>=1) s+=__shfl_down_sync(0xffffffffu,s,o);
    __shared__ float ws[8];
    if((threadIdx.x&31)==0) ws[threadIdx.x>>5]=s;
    __syncthreads();
    if(threadIdx.x<8){
        float t=ws[threadIdx.x];
        #pragma unroll
        for(int o=4;o>0;o>>=1) t+=__shfl_down_sync(0xffu,t,o);
        if(threadIdx.x==0) g_p[blockIdx.x]=t*(1.0f/1024.0f);
    }
}

// ---------------- k2: per-batch dynamic params ----------------
__global__ void __launch_bounds__(256) params_kernel(
    const float* __restrict__ kp_w1,const float* __restrict__ bng,const float* __restrict__ bnb,
    const float* __restrict__ bnm,const float* __restrict__ bnv,const float* __restrict__ kp_w2,
    const float* __restrict__ kp_b2,const float* __restrict__ fn_std,const float* __restrict__ fn_mean){
    int tid=threadIdx.x,b=blockIdx.x;
    __shared__ float ps[CC]; __shared__ float hs[CR];
    __shared__ float r1[256],r2[256]; __shared__ float uS,invS;
    for(int i=tid;i<CC;i+=256) ps[i]=g_p[b*CC+i];
    __syncthreads();
    if(tid<CR){
        float s=0.f; const float* wr=kp_w1+tid*CC;
        #pragma unroll 8
        for(int c=0;c<CC;++c) s+=ps[c]*wr[c];
        s=(s-bnm[tid])*rsqrtf(bnv[tid]+1e-5f)*bng[tid]+bnb[tid];
        hs[tid]=fmaxf(s,0.0f);
    }
    __syncthreads();
    float* gp=g_params+(size_t)b*P24K;
    float s1=0.f,s2=0.f;
    for(int i=tid;i<P24K;i+=256){
        const float* wr=kp_w2+(size_t)i*CR;
        float v=kp_b2[i];
        #pragma unroll
        for(int j=0;j<CR;++j) v+=hs[j]*wr[j];
        gp[i]=v; s1+=v; s2+=v*v;
    }
    r1[tid]=s1; r2[tid]=s2; __syncthreads();
    for(int o=128;o>0;o>>=1){ if(tid<o){r1[tid]+=r1[tid+o]; r2[tid]+=r2[tid+o];} __syncthreads(); }
    if(tid==0){
        float u=r1[0]*(1.0f/P24K);
        float var=r2[0]*(1.0f/P24K)-u*u;
        uS=u; invS=rsqrtf(var+1e-12f);
    }
    __syncthreads();
    float u=uS,inv=invS;
    for(int i=tid;i<P24K;i+=256){ float v=gp[i]; gp[i]=(v-u)*inv*fn_std[i]+fn_mean[i]; }
}

// ---------------- k3: circular conv + PE + bias (shfl-rotated taps) ----------------
__global__ void __launch_bounds__(256) conv_kernel(const float* __restrict__ x,
                                                   const float* __restrict__ bias){
    __shared__ float tile[32*33];
    __shared__ float pe_s[32];
    int tid=threadIdx.x,bc=blockIdx.x;
    int b=bc/CC,ch=bc%CC;
    const float* pb=g_params+(size_t)b*P24K;
    bool modeH=(ch<C2);
    const float* kb=modeH?(pb+(2*C2+ch)*32):(pb+(3*C2+(ch-C2))*32);
    const float* pe=modeH?(pb+ch*32):(pb+(C2+(ch-C2))*32);
    if(tid<32) pe_s[tid]=pe[tid];
    int lane=tid&31,h0=tid>>5;
    float kv=__ldg(&kb[lane]);
    __syncthreads();
    const float* xb=x+(size_t)bc*HW;
    #pragma unroll
    for(int r=0;r<4;++r){
        int idx=tid+r*256,g=idx>>5,w=idx&31;
        tile[g*33+w]=xb[idx]+(modeH?pe_s[g]:pe_s[w]);
    }
    __syncthreads();
    float bi=__ldg(&bias[ch]);
    float a0=0.f,a1=0.f,a2=0.f,a3=0.f,krot[32];
    if(modeH){
        #pragma unroll
        for(int g=0;g<32;++g) krot[g]=__shfl_sync(0xffffffffu,kv,(g-h0)&31);
        #pragma unroll
        for(int g=0;g<32;++g){
            float tv=tile[g*33+lane];
            a0+=krot[g]*tv;           a1+=krot[(g-8)&31]*tv;
            a2+=krot[(g-16)&31]*tv;   a3+=krot[(g-24)&31]*tv;
        }
    }else{
        #pragma unroll
        for(int v=0;v<32;++v) krot[v]=__shfl_sync(0xffffffffu,kv,(v-lane)&31);
        #pragma unroll
        for(int v=0;v<32;++v){
            float kvv=krot[v];
            a0+=kvv*tile[h0*33+v];        a1+=kvv*tile[(h0+8)*33+v];
            a2+=kvv*tile[(h0+16)*33+v];   a3+=kvv*tile[(h0+24)*33+v];
        }
    }
    float* yo=g_y+(size_t)bc*HW;
    yo[h0*32+lane]=a0+bi;        yo[(h0+8)*32+lane]=a1+bi;
    yo[(h0+16)*32+lane]=a2+bi;   yo[(h0+24)*32+lane]=a3+bi;
}

// ---------------- k4: channel LN -> token-major bf16 ----------------
__global__ void __launch_bounds__(256) ln_kernel(const float* __restrict__ ln_w,
                                                 const float* __restrict__ ln_b){
    int tid=threadIdx.x;
    int tok0=blockIdx.x*32;
    int b=tok0>>10,hw0=tok0&1023;
    int j=tid&31,cg=tid>>5;
    const float* yb=g_y+(size_t)b*CC*HW+hw0+j;
    float vals[48],s1=0.f,s2=0.f;
    #pragma unroll
    for(int i=0;i<48;++i){
        int c=cg+i*8;
        float v=yb[(size_t)c*HW];
        vals[i]=v; s1+=v; s2+=v*v;
    }
    __shared__ float rs1[8][32],rs2[8][32],muS[32],rstdS[32];
    rs1[cg][j]=s1; rs2[cg][j]=s2;
    __syncthreads();
    if(tid<32){
        float a=0.f,q=0.f;
        #pragma unroll
        for(int g=0;g<8;++g){a+=rs1[g][tid]; q+=rs2[g][tid];}
        float mu=a*(1.0f/CC);
        float var=q*(1.0f/CC)-mu*mu;
        muS[tid]=mu; rstdS[tid]=rsqrtf(var+1e-6f);
    }
    __syncthreads();
    __shared__ __nv_bfloat16 smo[32*386];
    float mu=muS[j],rsd=rstdS[j];
    #pragma unroll
    for(int i=0;i<48;++i){
        int c=cg+i*8;
        float t=(vals[i]-mu)*rsd*ln_w[c]+ln_b[c];
        smo[j*386+c]=__float2bfloat16(t);
    }
    __syncthreads();
    __nv_bfloat16* ao=g_aln+(size_t)tok0*CC;
    for(int idx=tid;idx<32*CC;idx+=256){
        int jj=idx/CC,ccx=idx-jj*CC;
        ao[idx]=smo[jj*386+ccx];
    }
}

// ---------------- bf16 GEMM mainloop: 128x128xK, BK=32, NS=4 stages, 1 barrier/ktile ----
template<int KDIM>
__device__ __forceinline__ void gemm_tile(const __nv_bfloat16* __restrict__ A,
                                          const __nv_bfloat16* __restrict__ W,
                                          int mBase,int nBase,float acc[2][8][4],
                                          __nv_bfloat16* As,__nv_bfloat16* Ws){
    const int tid=threadIdx.x;
    const int lane=tid&31,warp=tid>>5;
    const int wm=(warp&3)*32,wn=(warp>>2)*64;
    constexpr int KT=KDIM/32;

    auto load_stage=[&](int s,int kt){
        int k0=kt*32;
        __nv_bfloat16* as=As+s*(128*KPAD);
        __nv_bfloat16* ws=Ws+s*(128*KPAD);
        #pragma unroll
        for(int i=tid;i<512;i+=256){
            int row=i>>2,seg=(i&3)*8;
            cp16(as+row*KPAD+seg,A+(size_t)(mBase+row)*KDIM+k0+seg);
            cp16(ws+row*KPAD+seg,W+(size_t)(nBase+row)*KDIM+k0+seg);
        }
        cp_commit();
    };

    load_stage(0,0); load_stage(1,1); load_stage(2,2);

    for(int kt=0;kt<KT;++kt){
        int s=kt&(NS-1);
        cp_wait<NS-2>();
        __syncthreads();
        if(kt+NS-1<KT) load_stage((kt+NS-1)&(NS-1),kt+NS-1);
        else           cp_commit();     // keep group counting uniform
        __nv_bfloat16* as=As+s*(128*KPAD);
        __nv_bfloat16* ws=Ws+s*(128*KPAD);
        #pragma unroll
        for(int kk=0;kk<2;++kk){
            unsigned a[2][4],bq[4][4];
            #pragma unroll
            for(int mi=0;mi<2;++mi)
                ldm_x4(smem_u32(as+(wm+mi*16+(lane&15))*KPAD+kk*16+(lane>>4)*8),
                       a[mi][0],a[mi][1],a[mi][2],a[mi][3]);
            #pragma unroll
            for(int nq=0;nq<4;++nq)
                ldm_x4(smem_u32(ws+(wn+nq*16+(lane&15))*KPAD+kk*16+(lane>>4)*8),
                       bq[nq][0],bq[nq][1],bq[nq][2],bq[nq][3]);
            #pragma unroll
            for(int mi=0;mi<2;++mi)
                #pragma unroll
                for(int ni=0;ni<8;++ni){
                    int nq=ni>>1,hp=ni&1;
                    mma16816(acc[mi][ni],a[mi][0],a[mi][1],a[mi][2],a[mi][3],
                             bq[nq][hp],bq[nq][2+hp]);
                }
        }
    }
}

// ---------------- k5: GEMM1 + bias + exact GELU -> g_hid ----------------
__global__ void __launch_bounds__(256) gemm1_kernel(const float* __restrict__ b1){
    extern __shared__ __align__(16) __nv_bfloat16 sm[];
    __nv_bfloat16* As=sm;
    __nv_bfloat16* Ws=sm+NS*128*KPAD;
    float acc[2][8][4];
    #pragma unroll
    for(int i=0;i<2;++i)
        #pragma unroll
        for(int j=0;j<8;++j)
            #pragma unroll
            for(int k=0;k<4;++k) acc[i][j][k]=0.f;

    int mBase=blockIdx.y*128,nBase=blockIdx.x*128;
    gemm_tile<CC>(g_aln,g_w1b,mBase,nBase,acc,As,Ws);

    int lane=threadIdx.x&31,warp=threadIdx.x>>5;
    int wm=mBase+(warp&3)*32,wn=nBase+(warp>>2)*64;
    #pragma unroll
    for(int mi=0;mi<2;++mi)
        #pragma unroll
        for(int ni=0;ni<8;++ni){
            int n=wn+ni*8+(lane&3)*2;
            float bn0=__ldg(&b1[n]),bn1=__ldg(&b1[n+1]);
            int m=wm+mi*16+(lane>>2);
            float c0=acc[mi][ni][0]+bn0;
            float c1=acc[mi][ni][1]+bn1;
            float c2=acc[mi][ni][2]+bn0;
            float c3=acc[mi][ni][3]+bn1;
            c0=0.5f*c0*(1.0f+erff(c0*0.70710678118654752f));
            c1=0.5f*c1*(1.0f+erff(c1*0.70710678118654752f));
            c2=0.5f*c2*(1.0f+erff(c2*0.70710678118654752f));
            c3=0.5f*c3*(1.0f+erff(c3*0.70710678118654752f));
            *reinterpret_cast<__nv_bfloat162*>(&g_hid[(size_t)m*HID+n])=__floats2bfloat162_rn(c0,c1);
            *reinterpret_cast<__nv_bfloat162*>(&g_hid[(size_t)(m+8)*HID+n])=__floats2bfloat162_rn(c2,c3);
        }
}

// ---------------- k6: GEMM2 + bias + gamma*t + residual -> out ----------------
__global__ void __launch_bounds__(256) gemm2_kernel(const float* __restrict__ x,
                                                    const float* __restrict__ b2,
                                                    const float* __restrict__ gamma,
                                                    float* __restrict__ out){
    extern __shared__ __align__(16) __nv_bfloat16 sm[];
    __nv_bfloat16* As=sm;
    __nv_bfloat16* Ws=sm+NS*128*KPAD;
    float acc[2][8][4];
    #pragma unroll
    for(int i=0;i<2;++i)
        #pragma unroll
        for(int j=0;j<8;++j)
            #pragma unroll
            for(int k=0;k<4;++k) acc[i][j][k]=0.f;

    int mBase=blockIdx.y*128,nBase=blockIdx.x*128;
    gemm_tile<HID>(g_hid,g_w2b,mBase,nBase,acc,As,Ws);

    int lane=threadIdx.x&31,warp=threadIdx.x>>5;
    int wm=mBase+(warp&3)*32,wn=nBase+(warp>>2)*64;
    #pragma unroll
    for(int mi=0;mi<2;++mi)
        #pragma unroll
        for(int ni=0;ni<8;++ni){
            int n=wn+ni*8+(lane&3)*2;
            float bb0=__ldg(&b2[n]),bb1=__ldg(&b2[n+1]);
            float gm0=__ldg(&gamma[n]),gm1=__ldg(&gamma[n+1]);
            int m0=wm+mi*16+(lane>>2);
            #pragma unroll
            for(int half=0;half<2;++half){
                int m=m0+half*8;
                float v0=acc[mi][ni][half*2+0]+bb0;
                float v1=acc[mi][ni][half*2+1]+bb1;
                int b=m>>10,hw=m&1023;
                size_t i0=((size_t)(b*CC+n)<<10)+hw;
                out[i0]     =x[i0]     +gm0*v0;
                out[i0+1024]=x[i0+1024]+gm1*v1;
            }
        }
}

// ---------------- launch ----------------
extern "C" void kernel_launch(void* const* d_in, const int* in_sizes, int n_in,
                              void* d_out, int out_size) {
    const float* x       = (const float*)d_in[0];
    const float* kp_w1   = (const float*)d_in[1];
    const float* bng     = (const float*)d_in[2];
    const float* bnb     = (const float*)d_in[3];
    const float* bnm     = (const float*)d_in[4];
    const float* bnv     = (const float*)d_in[5];
    const float* kp_w2   = (const float*)d_in[6];
    const float* kp_b2   = (const float*)d_in[7];
    const float* fn_std  = (const float*)d_in[8];
    const float* fn_mean = (const float*)d_in[9];
    const float* bias    = (const float*)d_in[10];
    const float* ln_w    = (const float*)d_in[11];
    const float* ln_b    = (const float*)d_in[12];
    const float* w1      = (const float*)d_in[13];
    const float* b1      = (const float*)d_in[14];
    const float* w2      = (const float*)d_in[15];
    const float* b2      = (const float*)d_in[16];
    const float* gamma   = (const float*)d_in[17];
    float* out = (float*)d_out;

    static bool attr_set=false;
    if(!attr_set){
        cudaFuncSetAttribute(gemm1_kernel,cudaFuncAttributeMaxDynamicSharedMemorySize,GEMM_SMEM);
        cudaFuncSetAttribute(gemm2_kernel,cudaFuncAttributeMaxDynamicSharedMemorySize,GEMM_SMEM);
        attr_set=true;
    }

    cvt_w_kernel<<<(HID*CC+255)/256,256>>>(w1,w2);
    pool_kernel<<<BB*CC,256>>>(x);
    params_kernel<<<BB,256>>>(kp_w1,bng,bnb,bnm,bnv,kp_w2,kp_b2,fn_std,fn_mean);
    conv_kernel<<<BB*CC,256>>>(x,bias);
    ln_kernel<<<NTOK/32,256>>>(ln_w,ln_b);
    gemm1_kernel<<<dim3(HID/128,NTOK/128),256,GEMM_SMEM>>>(b1);
    gemm2_kernel<<<dim3(CC/128,NTOK/128),256,GEMM_SMEM>>>(x,b2,gamma,out);
}